// round 17
// baseline (speedup 1.0000x reference)
#include <cuda_runtime.h>
#include <cuda_bf16.h>
#include <cstdint>
#include <math.h>

#define BB 2
#define TT 2048
#define EE 1024
#define HH 16
#define DH 64
#define MM (BB*TT)   // 4096

// Scratch (__device__ globals; allocations are forbidden)
__device__ float          g_x1[MM*EE];          // attn+residual output (f32, FFN input)
__device__ float          g_wtf[EE*EE];         // Wf transposed [n][k] f32 (FFN B operand)
__device__ __nv_bfloat16  g_xh[MM*EE];          // x in bf16 (QKV A operand)
__device__ __nv_bfloat16  g_qh[MM*EE];
__device__ __nv_bfloat16  g_kh[MM*EE];
__device__ __nv_bfloat16  g_vh[MM*EE];
__device__ __nv_bfloat16  g_wh3[3*EE*EE];       // Wq,Wk,Wv bf16, NATURAL [k][n] layout

// ---------------------------------------------------------------------------
// Baseline-PTX helpers (sm_80-era: mma.sync + cp.async + ldmatrix).
// ---------------------------------------------------------------------------
__device__ __forceinline__ uint32_t smem_u32(const void* p){
    uint32_t a;
    asm("{ .reg .u64 t; cvta.to.shared.u64 t, %1; cvt.u32.u64 %0, t; }":"=r"(a):"l"(p));
    return a;
}
#define CP16(dst,src)  asm volatile("cp.async.cg.shared.global [%0], [%1], 16;\n"::"r"(dst),"l"(src))
#define CP_COMMIT()    asm volatile("cp.async.commit_group;\n":::"memory")
#define CP_WAIT1()     asm volatile("cp.async.wait_group 1;\n":::"memory")
#define CP_WAIT0()     asm volatile("cp.async.wait_group 0;\n":::"memory")
#define LDSM4(r0,r1,r2,r3,addr) \
    asm volatile("ldmatrix.sync.aligned.m8n8.x4.shared.b16 {%0,%1,%2,%3}, [%4];" \
        :"=r"(r0),"=r"(r1),"=r"(r2),"=r"(r3):"r"(addr))
#define LDSM4T(r0,r1,r2,r3,addr) \
    asm volatile("ldmatrix.sync.aligned.m8n8.x4.trans.shared.b16 {%0,%1,%2,%3}, [%4];" \
        :"=r"(r0),"=r"(r1),"=r"(r2),"=r"(r3):"r"(addr))

__device__ __forceinline__ void mma_tf32(float c[4], uint32_t a0, uint32_t a1,
                                         uint32_t a2, uint32_t a3,
                                         uint32_t b0, uint32_t b1){
    asm volatile(
        "mma.sync.aligned.m16n8k8.row.col.f32.tf32.tf32.f32 "
        "{%0,%1,%2,%3}, {%4,%5,%6,%7}, {%8,%9}, {%0,%1,%2,%3};\n"
        : "+f"(c[0]), "+f"(c[1]), "+f"(c[2]), "+f"(c[3])
        : "r"(a0), "r"(a1), "r"(a2), "r"(a3), "r"(b0), "r"(b1));
}
__device__ __forceinline__ void mma_bf16(float c[4], uint32_t a0, uint32_t a1,
                                         uint32_t a2, uint32_t a3,
                                         uint32_t b0, uint32_t b1){
    asm volatile(
        "mma.sync.aligned.m16n8k16.row.col.f32.bf16.bf16.f32 "
        "{%0,%1,%2,%3}, {%4,%5,%6,%7}, {%8,%9}, {%0,%1,%2,%3};\n"
        : "+f"(c[0]), "+f"(c[1]), "+f"(c[2]), "+f"(c[3])
        : "r"(a0), "r"(a1), "r"(a2), "r"(a3), "r"(b0), "r"(b1));
}
__device__ __forceinline__ float ex2f(float x){
    float y; asm("ex2.approx.f32 %0, %1;":"=f"(y):"f"(x)); return y;
}

// ---------------------------------------------------------------------------
// Prologue A (single launch): f32 -> bf16 for x, Wq, Wk, Wv.
// ---------------------------------------------------------------------------
#define XN (MM*EE)     // 4M
#define WN (EE*EE)     // 1M

__global__ void __launch_bounds__(256) cvt_all_kernel(const float* __restrict__ x,
                                                      const float* __restrict__ Wq,
                                                      const float* __restrict__ Wk,
                                                      const float* __restrict__ Wv)
{
    int i = (blockIdx.x * 256 + threadIdx.x) * 4;
    const float* src;
    __nv_bfloat16* dst;
    int off;
    if (i < XN) {
        src = x; dst = g_xh; off = i;
    } else {
        int j = i - XN;
        int slot = j >> 20;              // /WN
        off = j & (WN - 1);
        src = (slot == 0) ? Wq : (slot == 1) ? Wk : Wv;
        dst = g_wh3 + (size_t)slot * WN;
    }
    float4 v = *reinterpret_cast<const float4*>(src + off);
    __nv_bfloat162 p0 = __floats2bfloat162_rn(v.x, v.y);
    __nv_bfloat162 p1 = __floats2bfloat162_rn(v.z, v.w);
    uint2 u;
    u.x = *reinterpret_cast<uint32_t*>(&p0);
    u.y = *reinterpret_cast<uint32_t*>(&p1);
    *reinterpret_cast<uint2*>(&dst[off]) = u;
}

// ---------------------------------------------------------------------------
// Prologue B: Wf [k][n] -> g_wtf [n][k] f32 (enables B-operand ldmatrix in FFN)
// ---------------------------------------------------------------------------
__global__ void __launch_bounds__(256) tpose_f32_kernel(const float* __restrict__ W)
{
    __shared__ float t[32][33];
    int x  = blockIdx.x * 32 + threadIdx.x;   // n
    int y0 = blockIdx.y * 32;                 // k
    #pragma unroll
    for (int dy = threadIdx.y; dy < 32; dy += 8)
        t[dy][threadIdx.x] = W[(size_t)(y0 + dy) * EE + x];
    __syncthreads();
    int ko = y0 + threadIdx.x;
    int n0 = blockIdx.x * 32;
    #pragma unroll
    for (int dy = threadIdx.y; dy < 32; dy += 8)
        g_wtf[(size_t)(n0 + dy) * EE + ko] = t[threadIdx.x][dy];
}

// ---------------------------------------------------------------------------
// bf16 QKV GEMM (fused 3 projections): C = x @ W (proven R12 kernel).
// ---------------------------------------------------------------------------
#define HA_BYTES (128*80)          // 10240
#define WB_ROW   528               // 256 bf16 = 512B + 16B pad
#define WB_BYTES (32*WB_ROW)       // 16896
#define HSTAGE   (HA_BYTES + WB_BYTES)   // 27136
#define QKV_SMEM (2*HSTAGE)        // 54272

__global__ void __launch_bounds__(256) qkv_gemm()
{
    extern __shared__ char smc[];
    const uint32_t sbase = smem_u32(smc);
    const int tid  = threadIdx.x;
    const int wid  = tid >> 5, lane = tid & 31;
    const int ty   = lane >> 2, tx = lane & 3;
    const int wm   = wid >> 2;
    const int wn   = wid & 3;
    const int row0 = blockIdx.y * 128;
    const int sel  = blockIdx.x >> 2;
    const int col0 = (blockIdx.x & 3) * 256;
    const __nv_bfloat16* Wt = g_wh3 + (size_t)sel * WN;   // [k][n]
    __nv_bfloat16* C = (sel == 0) ? g_qh : (sel == 1) ? g_kh : g_vh;

    float c[4][8][4];
    #pragma unroll
    for (int mf = 0; mf < 4; mf++)
        #pragma unroll
        for (int nf = 0; nf < 8; nf++)
            #pragma unroll
            for (int u = 0; u < 4; u++) c[mf][nf][u] = 0.f;

    auto load_tiles = [&](int st, int k0){
        uint32_t sA = sbase + st * HSTAGE;
        uint32_t sB = sA + HA_BYTES;
        #pragma unroll
        for (int t = 0; t < 2; t++) {               // A: 128 rows x 4 chunks (32 bf16)
            int s = tid + t * 256;
            int r = s >> 2, ch = s & 3;
            CP16(sA + (uint32_t)(r * 80 + ch * 16),
                 g_xh + (size_t)(row0 + r) * EE + k0 + ch * 8);
        }
        #pragma unroll
        for (int t = 0; t < 4; t++) {               // B: 32 k-rows x 32 chunks (256 bf16)
            int s = tid + t * 256;
            int r = s >> 5, ch = s & 31;
            CP16(sB + (uint32_t)(r * WB_ROW + ch * 16),
                 Wt + (size_t)(k0 + r) * EE + col0 + ch * 8);
        }
    };

    load_tiles(0, 0);
    CP_COMMIT();

    for (int kt = 0; kt < 32; kt++) {
        const int b = kt & 1;
        if (kt + 1 < 32) {
            load_tiles(1 - b, (kt + 1) << 5);
            CP_COMMIT();
            CP_WAIT1();
        } else {
            CP_WAIT0();
        }
        __syncthreads();

        const uint32_t sA = sbase + b * HSTAGE;
        const uint32_t sB = sA + HA_BYTES;

        #pragma unroll
        for (int ks = 0; ks < 2; ks++) {
            uint32_t a[4][4];
            #pragma unroll
            for (int mf = 0; mf < 4; mf++) {
                uint32_t row = wm * 64 + mf * 16 + (lane & 15);
                uint32_t kh  = ks * 16 + ((lane & 16) >> 1);
                LDSM4(a[mf][0], a[mf][1], a[mf][2], a[mf][3],
                      sA + row * 80 + kh * 2);
            }
            uint32_t bfr[8][2];
            #pragma unroll
            for (int p = 0; p < 4; p++) {
                uint32_t krow = ks * 16 + (lane & 15);
                uint32_t nh   = wn * 64 + p * 16 + ((lane & 16) >> 1);
                LDSM4T(bfr[2*p][0], bfr[2*p][1], bfr[2*p+1][0], bfr[2*p+1][1],
                       sB + krow * WB_ROW + nh * 2);
            }
            #pragma unroll
            for (int mf = 0; mf < 4; mf++)
                #pragma unroll
                for (int nf = 0; nf < 8; nf++)
                    mma_bf16(c[mf][nf], a[mf][0], a[mf][1], a[mf][2], a[mf][3],
                             bfr[nf][0], bfr[nf][1]);
        }
        __syncthreads();
    }

    #pragma unroll
    for (int mf = 0; mf < 4; mf++) {
        const int r = row0 + wm * 64 + mf * 16 + ty;
        #pragma unroll
        for (int nf = 0; nf < 8; nf++) {
            const int cc = col0 + wn * 64 + nf * 8 + (tx << 1);
            __nv_bfloat162 p0 = __floats2bfloat162_rn(c[mf][nf][0], c[mf][nf][1]);
            __nv_bfloat162 p1 = __floats2bfloat162_rn(c[mf][nf][2], c[mf][nf][3]);
            *reinterpret_cast<__nv_bfloat162*>(&C[(size_t)r * EE + cc]) = p0;
            *reinterpret_cast<__nv_bfloat162*>(&C[(size_t)(r + 8) * EE + cc]) = p1;
        }
    }
}

// ---------------------------------------------------------------------------
// bf16 flash attention (proven R12 kernel, heavy-first order kept).
// ---------------------------------------------------------------------------
#define QT 128
#define AST 72                                  // halfwords per row
#define AT_BYTES (64*AST*2)                     // 9216 per stage
#define ATTN_SMEM (4*AT_BYTES)                  // 36864: KS[2] + VS[2]

__global__ void __launch_bounds__(256, 1) attn_tc(const float* __restrict__ x)
{
    extern __shared__ char smc[];
    const uint32_t sb_KS = smem_u32(smc);
    const uint32_t sb_VS = sb_KS + 2 * AT_BYTES;

    const int tid = threadIdx.x;
    const int wid = tid >> 5, lane = tid & 31;
    const int ty = lane >> 2, tx = lane & 3;
    const int bh = blockIdx.y, b = bh >> 4, h = bh & 15;
    const int qb = (gridDim.x - 1 - blockIdx.x) * QT;   // heavy-first
    const int ktmax = (qb + QT - 1) >> 6;
    const float sc2 = 0.03125f * 1.44269504088896f;     // 1/sqrt(1024) * log2e

    {
        const __nv_bfloat16* Qg = g_qh + (size_t)(b * TT + qb) * EE + h * DH;
        #pragma unroll
        for (int t = 0; t < 4; t++) {
            int s = tid + t * 256;
            int r = s >> 3, ch = s & 7;
            CP16(sb_KS + (uint32_t)(r * 144 + ch * 16), Qg + (size_t)r * EE + ch * 8);
        }
        CP_COMMIT(); CP_WAIT0();
    }
    __syncthreads();

    uint32_t qa[4][4];
    #pragma unroll
    for (int kf = 0; kf < 4; kf++) {
        uint32_t row = wid * 16 + (lane & 15);
        uint32_t kh  = kf * 16 + ((lane & 16) >> 1);
        LDSM4(qa[kf][0], qa[kf][1], qa[kf][2], qa[kf][3],
              sb_KS + row * 144 + kh * 2);
    }
    __syncthreads();

    float mrow[2] = {-1e30f, -1e30f};
    float lrow[2] = {0.f, 0.f};
    float o[8][4];
    #pragma unroll
    for (int df = 0; df < 8; df++)
        #pragma unroll
        for (int u = 0; u < 4; u++) o[df][u] = 0.f;

    auto issue_tile = [&](int kt){
        const __nv_bfloat16* Kg = g_kh + (size_t)(b * TT + kt * 64) * EE + h * DH;
        const __nv_bfloat16* Vg = g_vh + (size_t)(b * TT + kt * 64) * EE + h * DH;
        uint32_t dK = sb_KS + (uint32_t)((kt & 1) * AT_BYTES);
        uint32_t dV = sb_VS + (uint32_t)((kt & 1) * AT_BYTES);
        #pragma unroll
        for (int t = 0; t < 2; t++) {
            int s = tid + t * 256;
            int r = s >> 3, ch = s & 7;
            CP16(dK + (uint32_t)(r * 144 + ch * 16), Kg + (size_t)r * EE + ch * 8);
            CP16(dV + (uint32_t)(r * 144 + ch * 16), Vg + (size_t)r * EE + ch * 8);
        }
        CP_COMMIT();
    };

    issue_tile(0);
    issue_tile(1);

    for (int kt = 0; kt <= ktmax; kt++) {
        const int bs = kt & 1;
        if (kt < ktmax) { CP_WAIT1(); } else { CP_WAIT0(); }
        __syncthreads();

        const uint32_t sK = sb_KS + bs * AT_BYTES;
        const uint32_t sV = sb_VS + bs * AT_BYTES;

        float s[8][4];
        #pragma unroll
        for (int nf = 0; nf < 8; nf++)
            #pragma unroll
            for (int u = 0; u < 4; u++) s[nf][u] = 0.f;
        #pragma unroll
        for (int kf = 0; kf < 4; kf++) {
            uint32_t bk[8][2];
            #pragma unroll
            for (int p = 0; p < 4; p++) {
                uint32_t row = p * 16 + (lane & 7) + ((lane & 16) >> 1);
                uint32_t kh  = kf * 16 + (lane & 8);
                LDSM4(bk[2*p][0], bk[2*p][1], bk[2*p+1][0], bk[2*p+1][1],
                      sK + row * 144 + kh * 2);
            }
            #pragma unroll
            for (int nf = 0; nf < 8; nf++)
                mma_bf16(s[nf], qa[kf][0], qa[kf][1], qa[kf][2], qa[kf][3],
                         bk[nf][0], bk[nf][1]);
        }

        const int q0 = qb + wid * 16;
        const bool need_mask = (kt * 64 + 63) > q0;
        float pmax[2] = {-1e30f, -1e30f};
        #pragma unroll
        for (int nf = 0; nf < 8; nf++) {
            int kkb = kt * 64 + nf * 8 + 2 * tx;
            #pragma unroll
            for (int u = 0; u < 4; u++) {
                float v = s[nf][u] * sc2;
                if (need_mask) {
                    int kkg = kkb + (u & 1);
                    int qg  = q0 + ty + ((u >> 1) << 3);
                    if (kkg > qg) v = -1e30f;
                }
                s[nf][u] = v;
                pmax[u >> 1] = fmaxf(pmax[u >> 1], v);
            }
        }
        #pragma unroll
        for (int r = 0; r < 2; r++) {
            pmax[r] = fmaxf(pmax[r], __shfl_xor_sync(0xffffffffu, pmax[r], 1));
            pmax[r] = fmaxf(pmax[r], __shfl_xor_sync(0xffffffffu, pmax[r], 2));
        }
        float mn0 = fmaxf(mrow[0], pmax[0]);
        float mn1 = fmaxf(mrow[1], pmax[1]);
        float cr0 = ex2f(mrow[0] - mn0);
        float cr1 = ex2f(mrow[1] - mn1);
        mrow[0] = mn0; mrow[1] = mn1;

        uint32_t pa[4][4];
        float ls[2] = {0.f, 0.f};
        #pragma unroll
        for (int nf = 0; nf < 8; nf++) {
            float p0 = ex2f(s[nf][0] - mn0);
            float p1 = ex2f(s[nf][1] - mn0);
            float p2 = ex2f(s[nf][2] - mn1);
            float p3 = ex2f(s[nf][3] - mn1);
            ls[0] += p0 + p1;
            ls[1] += p2 + p3;
            __nv_bfloat162 t0 = __floats2bfloat162_rn(p0, p1);
            __nv_bfloat162 t1 = __floats2bfloat162_rn(p2, p3);
            uint32_t lo = *reinterpret_cast<uint32_t*>(&t0);
            uint32_t hi = *reinterpret_cast<uint32_t*>(&t1);
            int kb = nf >> 1;
            if ((nf & 1) == 0) { pa[kb][0] = lo; pa[kb][1] = hi; }
            else               { pa[kb][2] = lo; pa[kb][3] = hi; }
        }
        #pragma unroll
        for (int r = 0; r < 2; r++) {
            ls[r] += __shfl_xor_sync(0xffffffffu, ls[r], 1);
            ls[r] += __shfl_xor_sync(0xffffffffu, ls[r], 2);
        }
        lrow[0] = lrow[0] * cr0 + ls[0];
        lrow[1] = lrow[1] * cr1 + ls[1];

        #pragma unroll
        for (int df = 0; df < 8; df++) {
            o[df][0] *= cr0; o[df][1] *= cr0;
            o[df][2] *= cr1; o[df][3] *= cr1;
        }
        #pragma unroll
        for (int kb = 0; kb < 4; kb++) {
            uint32_t vb[8][2];
            #pragma unroll
            for (int dp = 0; dp < 4; dp++) {
                uint32_t row = kb * 16 + (lane & 15);
                uint32_t dhh = dp * 16 + ((lane & 16) >> 1);
                LDSM4T(vb[2*dp][0], vb[2*dp][1], vb[2*dp+1][0], vb[2*dp+1][1],
                       sV + row * 144 + dhh * 2);
            }
            #pragma unroll
            for (int df = 0; df < 8; df++)
                mma_bf16(o[df], pa[kb][0], pa[kb][1], pa[kb][2], pa[kb][3],
                         vb[df][0], vb[df][1]);
        }
        __syncthreads();
        if (kt + 2 <= ktmax) issue_tile(kt + 2);
    }

    const float inv0 = 1.f / lrow[0];
    const float inv1 = 1.f / lrow[1];
    const size_t base = (size_t)(b * TT + qb + wid * 16) * EE + h * DH;
    #pragma unroll
    for (int df = 0; df < 8; df++) {
        int col = df * 8 + 2 * tx;
        {
            size_t idx = base + (size_t)ty * EE + col;
            float2 xv = *reinterpret_cast<const float2*>(&x[idx]);
            float2 ov = make_float2(xv.x + o[df][0] * inv0, xv.y + o[df][1] * inv0);
            *reinterpret_cast<float2*>(&g_x1[idx]) = ov;
        }
        {
            size_t idx = base + (size_t)(ty + 8) * EE + col;
            float2 xv = *reinterpret_cast<const float2*>(&x[idx]);
            float2 ov = make_float2(xv.x + o[df][2] * inv1, xv.y + o[df][3] * inv1);
            *reinterpret_cast<float2*>(&g_x1[idx]) = ov;
        }
    }
}

// ---------------------------------------------------------------------------
// FFN GEMM (tf32, precision-preserving) with ALL-LDMATRIX fragment loads.
// tf32 m16n8k8 fragments == bf16 m16n8k16 fragments on the b16-pair view:
//   A: [m][k] f32, 144B rows -> non-trans LDSM4 gives a0..a3 directly.
//   B: g_wtf [n][k] f32, 144B rows -> non-trans LDSM4 over 16 n-rows gives
//      {b0(nf even), b0(nf odd), b1(nf even), b1(nf odd)} per k-step.
// Numerics identical to the scalar-LDS version (same values, same mma order).
// out = x1 + relu(x1 @ Wf + bias). CTA 128x256, BK=32.
// ---------------------------------------------------------------------------
#define F_ST    36                      // f32 per smem row (32 data + 4 pad) = 144B
#define FA_BYTES (128*F_ST*4)           // 18432
#define FB_BYTES (256*F_ST*4)           // 36864
#define FSTAGE   (FA_BYTES + FB_BYTES)  // 55296
#define GEMM_SMEM (2*FSTAGE)            // 110592

__global__ void __launch_bounds__(256) ffn_gemm(const float* __restrict__ A,
                                                float* __restrict__ C,
                                                const float* __restrict__ bias)
{
    extern __shared__ char smc[];
    const uint32_t sbase = smem_u32(smc);
    const int tid  = threadIdx.x;
    const int wid  = tid >> 5, lane = tid & 31;
    const int ty   = lane >> 2, tx = lane & 3;
    const int wm   = wid >> 2;
    const int wn   = wid & 3;
    const int row0 = blockIdx.y * 128;
    const int col0 = blockIdx.x * 256;

    float c[4][8][4];
    #pragma unroll
    for (int mf = 0; mf < 4; mf++)
        #pragma unroll
        for (int nf = 0; nf < 8; nf++)
            #pragma unroll
            for (int u = 0; u < 4; u++) c[mf][nf][u] = 0.f;

    auto load_tiles = [&](int st, int k0){
        uint32_t sA = sbase + st * FSTAGE;
        uint32_t sB = sA + FA_BYTES;
        #pragma unroll
        for (int t = 0; t < 4; t++) {            // A: 128 rows x 8 chunks of 16B
            int s  = tid + t * 256;
            int r  = s >> 3, ch = s & 7;
            CP16(sA + (uint32_t)(r * 144 + ch * 16),
                 A + (size_t)(row0 + r) * EE + k0 + ch * 4);
        }
        #pragma unroll
        for (int t = 0; t < 8; t++) {            // B: 256 n-rows x 8 chunks of 16B
            int s  = tid + t * 256;
            int r  = s >> 3, ch = s & 7;
            CP16(sB + (uint32_t)(r * 144 + ch * 16),
                 g_wtf + (size_t)(col0 + r) * EE + k0 + ch * 4);
        }
    };

    load_tiles(0, 0);
    CP_COMMIT();

    for (int kt = 0; kt < 32; kt++) {
        const int b = kt & 1;
        if (kt + 1 < 32) {
            load_tiles(1 - b, (kt + 1) << 5);
            CP_COMMIT();
            CP_WAIT1();
        } else {
            CP_WAIT0();
        }
        __syncthreads();

        const uint32_t sA = sbase + b * FSTAGE;
        const uint32_t sB = sA + FA_BYTES;

        #pragma unroll
        for (int ks = 0; ks < 4; ks++) {
            const uint32_t kb = ks * 32;                 // byte offset of k8-block
            const uint32_t hi16 = (lane & 16) ? 16u : 0u;
            uint32_t a[4][4];
            #pragma unroll
            for (int mf = 0; mf < 4; mf++) {
                uint32_t row = wm * 64 + mf * 16 + (lane & 15);
                LDSM4(a[mf][0], a[mf][1], a[mf][2], a[mf][3],
                      sA + row * 144 + kb + hi16);
            }
            uint32_t bfr[8][2];
            #pragma unroll
            for (int p = 0; p < 4; p++) {
                uint32_t nrow = wn * 64 + p * 16 + (lane & 15);
                LDSM4(bfr[2*p][0], bfr[2*p+1][0], bfr[2*p][1], bfr[2*p+1][1],
                      sB + nrow * 144 + kb + hi16);
            }
            #pragma unroll
            for (int mf = 0; mf < 4; mf++)
                #pragma unroll
                for (int nf = 0; nf < 8; nf++)
                    mma_tf32(c[mf][nf], a[mf][0], a[mf][1], a[mf][2], a[mf][3],
                             bfr[nf][0], bfr[nf][1]);
        }
        __syncthreads();
    }

    #pragma unroll
    for (int mf = 0; mf < 4; mf++) {
        const int r = row0 + wm * 64 + mf * 16 + ty;
        #pragma unroll
        for (int nf = 0; nf < 8; nf++) {
            const int cc = col0 + wn * 64 + nf * 8 + (tx << 1);
            float2 v0 = make_float2(c[mf][nf][0], c[mf][nf][1]);
            float2 v1 = make_float2(c[mf][nf][2], c[mf][nf][3]);
            float2 bb = *reinterpret_cast<const float2*>(bias + cc);
            float2 x0 = *reinterpret_cast<const float2*>(A + (size_t)r * EE + cc);
            float2 x1 = *reinterpret_cast<const float2*>(A + (size_t)(r + 8) * EE + cc);
            v0.x = x0.x + fmaxf(v0.x + bb.x, 0.f);
            v0.y = x0.y + fmaxf(v0.y + bb.y, 0.f);
            v1.x = x1.x + fmaxf(v1.x + bb.x, 0.f);
            v1.y = x1.y + fmaxf(v1.y + bb.y, 0.f);
            *reinterpret_cast<float2*>(C + (size_t)r * EE + cc) = v0;
            *reinterpret_cast<float2*>(C + (size_t)(r + 8) * EE + cc) = v1;
        }
    }
}

// ---------------------------------------------------------------------------
extern "C" void kernel_launch(void* const* d_in, const int* in_sizes, int n_in,
                              void* d_out, int out_size)
{
    const float* x  = (const float*)d_in[0];
    const float* Wq = (const float*)d_in[1];
    const float* Wk = (const float*)d_in[2];
    const float* Wv = (const float*)d_in[3];
    const float* Wf = (const float*)d_in[4];
    const float* bf = (const float*)d_in[5];
    float* out = (float*)d_out;

    float* gx1;
    cudaGetSymbolAddress((void**)&gx1, g_x1);

    cudaFuncSetAttribute((const void*)qkv_gemm, cudaFuncAttributeMaxDynamicSharedMemorySize, QKV_SMEM);
    cudaFuncSetAttribute((const void*)attn_tc,  cudaFuncAttributeMaxDynamicSharedMemorySize, ATTN_SMEM);
    cudaFuncSetAttribute((const void*)ffn_gemm, cudaFuncAttributeMaxDynamicSharedMemorySize, GEMM_SMEM);

    // prologue: fused f32->bf16 conversion + Wf f32 transpose
    cvt_all_kernel<<<(XN + 3*WN) / 1024, 256>>>(x, Wq, Wk, Wv);
    tpose_f32_kernel<<<dim3(32, 32), dim3(32, 8)>>>(Wf);

    // fused QKV projections (bf16 tensor cores): 12 x 32 = 384 CTAs
    qkv_gemm<<<dim3(12, MM/128), 256, QKV_SMEM>>>();

    // bf16 flash attention + residual
    attn_tc<<<dim3(TT/QT, BB*HH), 256, ATTN_SMEM>>>(x);

    // FFN (tf32, all-ldmatrix) + bias + relu + residual
    ffn_gemm<<<dim3(4, MM/128), 256, GEMM_SMEM>>>(gx1, out, bf);
}